// round 2
// baseline (speedup 1.0000x reference)
#include <cuda_runtime.h>
#include <math.h>

#define TT 2048
#define HH 1024
#define FF 1024
#define EE 8

// ---------------- scratch (device globals; no allocation allowed) ----------
__device__ int   g_cnt[EE];
__device__ int   g_tok[EE][TT];
__device__ float g_wt [EE][TT];
__device__ float g_act[EE][TT][FF];   // routed silu(g)*u activations (64 MB)
__device__ float g_sact[TT][FF];      // shared-expert activations (8 MB)

// ---------------- init: zero counters + zero any tail (aux_loss) -----------
__global__ void init_kernel(float* __restrict__ out, int out_size) {
    int i = blockIdx.x * blockDim.x + threadIdx.x;
    if (i < EE) g_cnt[i] = 0;
    int tail = out_size - TT * HH;
    if (i < tail) out[TT * HH + i] = 0.0f;
}

// ---------------- router: logits, top-2, softmax, scatter ------------------
__global__ void router_kernel(const float* __restrict__ x,
                              const float* __restrict__ wg) {
    int warp = (blockIdx.x * blockDim.x + threadIdx.x) >> 5;
    int lane = threadIdx.x & 31;
    if (warp >= TT) return;
    const float* xr = x + (size_t)warp * HH;

    float acc[EE];
#pragma unroll
    for (int e = 0; e < EE; e++) acc[e] = 0.0f;

    for (int h = lane; h < HH; h += 32) {
        float xv = xr[h];
        const float4* w4 = (const float4*)(wg + (size_t)h * EE);
        float4 a = w4[0], b = w4[1];
        acc[0] += xv * a.x; acc[1] += xv * a.y;
        acc[2] += xv * a.z; acc[3] += xv * a.w;
        acc[4] += xv * b.x; acc[5] += xv * b.y;
        acc[6] += xv * b.z; acc[7] += xv * b.w;
    }
#pragma unroll
    for (int e = 0; e < EE; e++)
#pragma unroll
        for (int o = 16; o > 0; o >>= 1)
            acc[e] += __shfl_xor_sync(0xffffffffu, acc[e], o);

    if (lane == 0) {
        // top-2 with first-index tie-break (matches jax.lax.top_k)
        int i0 = 0; float v0 = acc[0];
#pragma unroll
        for (int e = 1; e < EE; e++) if (acc[e] > v0) { v0 = acc[e]; i0 = e; }
        int i1 = -1; float v1 = -INFINITY;
#pragma unroll
        for (int e = 0; e < EE; e++) {
            if (e == i0) continue;
            if (acc[e] > v1) { v1 = acc[e]; i1 = e; }
        }
        // softmax over [v0, v1] with v0 >= v1
        float ex = expf(v1 - v0);
        float inv = 1.0f / (1.0f + ex);
        float w0 = inv;
        float w1 = ex * inv;

        int p0 = atomicAdd(&g_cnt[i0], 1);
        g_tok[i0][p0] = warp; g_wt[i0][p0] = w0;
        int p1 = atomicAdd(&g_cnt[i1], 1);
        g_tok[i1][p1] = warp; g_wt[i1][p1] = w1;
    }
}

// ---------------- fused gate+up GEMM with SiLU epilogue --------------------
// C_act[m][n] = silu(sum_k A[m][k]*Wg[k][n]) * (sum_k A[m][k]*Wu[k][n])
// GATHER: rows gathered through g_tok[e], output into g_act[e]
// !GATHER: dense rows 0..TT-1, output into g_sact
template <bool GATHER>
__global__ void gemm_gateup(const float* __restrict__ X,
                            const float* __restrict__ Wg_all,
                            const float* __restrict__ Wu_all) {
    const int e  = GATHER ? blockIdx.z : 0;
    const int M  = GATHER ? g_cnt[e] : TT;
    const int m0 = blockIdx.y * 64;
    if (m0 >= M) return;
    const int n0 = blockIdx.x * 64;

    const float* Wg = Wg_all + (GATHER ? (size_t)e * HH * FF : 0);
    const float* Wu = Wu_all + (GATHER ? (size_t)e * HH * FF : 0);

    __shared__ float As[16][64];
    __shared__ float Bg[16][64];
    __shared__ float Bu[16][64];

    const int tid = threadIdx.x;
    const int tx  = tid & 15;   // n direction (4 cols each)
    const int ty  = tid >> 4;   // m direction (4 rows each)

    // A tile load mapping: 64 rows x 16 k, float4 per thread
    const int am = tid >> 2;          // 0..63
    const int ak = (tid & 3) * 4;     // 0,4,8,12
    const int arow = m0 + am;
    const bool avalid = (arow < M);
    const float* Arow = nullptr;
    if (avalid) {
        int tok = GATHER ? g_tok[e][arow] : arow;
        Arow = X + (size_t)tok * HH;
    }
    // B tile load mapping: 16 k x 64 n, float4 per thread
    const int bk = tid >> 4;          // 0..15
    const int bn = (tid & 15) * 4;    // 0..60

    float accg[4][4];
    float accu[4][4];
#pragma unroll
    for (int i = 0; i < 4; i++)
#pragma unroll
        for (int j = 0; j < 4; j++) { accg[i][j] = 0.0f; accu[i][j] = 0.0f; }

    for (int kk = 0; kk < HH; kk += 16) {
        float4 av = make_float4(0.f, 0.f, 0.f, 0.f);
        if (avalid) av = *(const float4*)(Arow + kk + ak);
        As[ak + 0][am] = av.x;
        As[ak + 1][am] = av.y;
        As[ak + 2][am] = av.z;
        As[ak + 3][am] = av.w;
        *(float4*)&Bg[bk][bn] = *(const float4*)(Wg + (size_t)(kk + bk) * FF + n0 + bn);
        *(float4*)&Bu[bk][bn] = *(const float4*)(Wu + (size_t)(kk + bk) * FF + n0 + bn);
        __syncthreads();
#pragma unroll
        for (int k = 0; k < 16; k++) {
            float4 a4  = *(const float4*)&As[k][ty * 4];
            float4 bg4 = *(const float4*)&Bg[k][tx * 4];
            float4 bu4 = *(const float4*)&Bu[k][tx * 4];
            float ar[4]  = {a4.x,  a4.y,  a4.z,  a4.w};
            float bgr[4] = {bg4.x, bg4.y, bg4.z, bg4.w};
            float bur[4] = {bu4.x, bu4.y, bu4.z, bu4.w};
#pragma unroll
            for (int i = 0; i < 4; i++)
#pragma unroll
                for (int j = 0; j < 4; j++) {
                    accg[i][j] += ar[i] * bgr[j];
                    accu[i][j] += ar[i] * bur[j];
                }
        }
        __syncthreads();
    }

#pragma unroll
    for (int i = 0; i < 4; i++) {
        int m = m0 + ty * 4 + i;
        if (m >= M) continue;
        float* orow = GATHER ? &g_act[e][m][0] : &g_sact[m][0];
        float4 o;
        float g, u, s;
        g = accg[i][0]; u = accu[i][0]; s = g / (1.0f + expf(-g)); o.x = s * u;
        g = accg[i][1]; u = accu[i][1]; s = g / (1.0f + expf(-g)); o.y = s * u;
        g = accg[i][2]; u = accu[i][2]; s = g / (1.0f + expf(-g)); o.z = s * u;
        g = accg[i][3]; u = accu[i][3]; s = g / (1.0f + expf(-g)); o.w = s * u;
        *(float4*)&orow[n0 + tx * 4] = o;
    }
}

// ---------------- down-proj GEMM ------------------------------------------
// EXPERT: A = g_act[e] (contiguous rows), scatter atomicAdd into out with
//         per-row weight. !EXPERT: A = g_sact, plain store (initializes out).
template <bool EXPERT>
__global__ void gemm_down(const float* __restrict__ Wd_all,
                          float* __restrict__ out) {
    const int e  = EXPERT ? blockIdx.z : 0;
    const int M  = EXPERT ? g_cnt[e] : TT;
    const int m0 = blockIdx.y * 64;
    if (m0 >= M) return;
    const int n0 = blockIdx.x * 64;

    const float* Wd   = Wd_all + (EXPERT ? (size_t)e * FF * HH : 0);
    const float* Asrc = EXPERT ? &g_act[e][0][0] : &g_sact[0][0];

    __shared__ float As[16][64];
    __shared__ float Bs[16][64];

    const int tid = threadIdx.x;
    const int tx  = tid & 15;
    const int ty  = tid >> 4;

    const int am = tid >> 2;
    const int ak = (tid & 3) * 4;
    const int arow = m0 + am;
    const bool avalid = (arow < M);
    const float* Arow = avalid ? (Asrc + (size_t)arow * FF) : nullptr;

    const int bk = tid >> 4;
    const int bn = (tid & 15) * 4;

    float acc[4][4];
#pragma unroll
    for (int i = 0; i < 4; i++)
#pragma unroll
        for (int j = 0; j < 4; j++) acc[i][j] = 0.0f;

    for (int kk = 0; kk < FF; kk += 16) {
        float4 av = make_float4(0.f, 0.f, 0.f, 0.f);
        if (avalid) av = *(const float4*)(Arow + kk + ak);
        As[ak + 0][am] = av.x;
        As[ak + 1][am] = av.y;
        As[ak + 2][am] = av.z;
        As[ak + 3][am] = av.w;
        *(float4*)&Bs[bk][bn] = *(const float4*)(Wd + (size_t)(kk + bk) * HH + n0 + bn);
        __syncthreads();
#pragma unroll
        for (int k = 0; k < 16; k++) {
            float4 a4 = *(const float4*)&As[k][ty * 4];
            float4 b4 = *(const float4*)&Bs[k][tx * 4];
            float ar[4] = {a4.x, a4.y, a4.z, a4.w};
            float br[4] = {b4.x, b4.y, b4.z, b4.w};
#pragma unroll
            for (int i = 0; i < 4; i++)
#pragma unroll
                for (int j = 0; j < 4; j++)
                    acc[i][j] += ar[i] * br[j];
        }
        __syncthreads();
    }

#pragma unroll
    for (int i = 0; i < 4; i++) {
        int m = m0 + ty * 4 + i;
        if (m >= M) continue;
        if (EXPERT) {
            int tok = g_tok[e][m];
            float w = g_wt[e][m];
            float* orow = out + (size_t)tok * HH + n0 + tx * 4;
            atomicAdd(&orow[0], w * acc[i][0]);
            atomicAdd(&orow[1], w * acc[i][1]);
            atomicAdd(&orow[2], w * acc[i][2]);
            atomicAdd(&orow[3], w * acc[i][3]);
        } else {
            float4 o = make_float4(acc[i][0], acc[i][1], acc[i][2], acc[i][3]);
            *(float4*)&out[(size_t)m * HH + n0 + tx * 4] = o;
        }
    }
}

// ---------------- launch ---------------------------------------------------
extern "C" void kernel_launch(void* const* d_in, const int* in_sizes, int n_in,
                              void* d_out, int out_size) {
    const float* x   = (const float*)d_in[0];  // [1,2048,1024]
    const float* wg  = (const float*)d_in[1];  // [1024,8]
    const float* wgp = (const float*)d_in[2];  // [8,1024,1024]
    const float* wup = (const float*)d_in[3];  // [8,1024,1024]
    const float* wdp = (const float*)d_in[4];  // [8,1024,1024]
    const float* wsg = (const float*)d_in[5];  // [1024,1024]
    const float* wsu = (const float*)d_in[6];  // [1024,1024]
    const float* wsd = (const float*)d_in[7];  // [1024,1024]
    float* out = (float*)d_out;

    int tail = out_size - TT * HH;
    int init_n = (tail > EE ? tail : EE);
    init_kernel<<<(init_n + 255) / 256, 256>>>(out, out_size);

    router_kernel<<<TT / 8, 256>>>(x, wg);   // 8 warps/block

    dim3 gs1(FF / 64, TT / 64, 1);
    gemm_gateup<false><<<gs1, 256>>>(x, wsg, wsu);

    dim3 ge1(FF / 64, TT / 64, EE);
    gemm_gateup<true><<<ge1, 256>>>(x, wgp, wup);

    dim3 gs2(HH / 64, TT / 64, 1);
    gemm_down<false><<<gs2, 256>>>(wsd, out);   // plain store: initializes out

    dim3 ge2(HH / 64, TT / 64, EE);
    gemm_down<true><<<ge2, 256>>>(wdp, out);    // weighted atomicAdd combine
}

// round 3
// speedup vs baseline: 4.3031x; 4.3031x over previous
#include <cuda_runtime.h>
#include <math.h>
#include <stdint.h>

#define TT 2048
#define HH 1024
#define FF 1024
#define EE 8

// ---------------- scratch (device globals; no allocation allowed) ----------
__device__ int   g_cnt[EE];
__device__ int   g_tok[EE][TT];
__device__ float g_wt [EE][TT];
__device__ float g_act[EE][TT][FF];   // routed silu(g)*u activations (64 MB)
__device__ float g_sact[TT][FF];      // shared-expert activations (8 MB)

// ---------------- helpers ---------------------------------------------------
__device__ __forceinline__ uint32_t f2tf32(float f) {
    uint32_t u;
    asm("cvt.rna.tf32.f32 %0, %1;" : "=r"(u) : "f"(f));
    return u;
}

__device__ __forceinline__ void mma8(float* c, const uint32_t* a, const uint32_t* b) {
    asm volatile(
        "mma.sync.aligned.m16n8k8.row.col.f32.tf32.tf32.f32 "
        "{%0,%1,%2,%3}, {%4,%5,%6,%7}, {%8,%9}, {%0,%1,%2,%3};"
        : "+f"(c[0]), "+f"(c[1]), "+f"(c[2]), "+f"(c[3])
        : "r"(a[0]), "r"(a[1]), "r"(a[2]), "r"(a[3]), "r"(b[0]), "r"(b[1]));
}

__device__ __forceinline__ uint4 cvt4(float4 v) {
    return make_uint4(f2tf32(v.x), f2tf32(v.y), f2tf32(v.z), f2tf32(v.w));
}

// ---------------- init: zero counters + zero any tail (aux_loss) -----------
__global__ void init_kernel(float* __restrict__ out, int out_size) {
    int i = blockIdx.x * blockDim.x + threadIdx.x;
    if (i < EE) g_cnt[i] = 0;
    int tail = out_size - TT * HH;
    if (i < tail) out[TT * HH + i] = 0.0f;
}

// ---------------- router: logits, top-2, softmax, scatter ------------------
__global__ void router_kernel(const float* __restrict__ x,
                              const float* __restrict__ wg) {
    int warp = (blockIdx.x * blockDim.x + threadIdx.x) >> 5;
    int lane = threadIdx.x & 31;
    if (warp >= TT) return;
    const float* xr = x + (size_t)warp * HH;

    float acc[EE];
#pragma unroll
    for (int e = 0; e < EE; e++) acc[e] = 0.0f;

    for (int h = lane; h < HH; h += 32) {
        float xv = xr[h];
        const float4* w4 = (const float4*)(wg + (size_t)h * EE);
        float4 a = w4[0], b = w4[1];
        acc[0] += xv * a.x; acc[1] += xv * a.y;
        acc[2] += xv * a.z; acc[3] += xv * a.w;
        acc[4] += xv * b.x; acc[5] += xv * b.y;
        acc[6] += xv * b.z; acc[7] += xv * b.w;
    }
#pragma unroll
    for (int e = 0; e < EE; e++)
#pragma unroll
        for (int o = 16; o > 0; o >>= 1)
            acc[e] += __shfl_xor_sync(0xffffffffu, acc[e], o);

    if (lane == 0) {
        int i0 = 0; float v0 = acc[0];
#pragma unroll
        for (int e = 1; e < EE; e++) if (acc[e] > v0) { v0 = acc[e]; i0 = e; }
        int i1 = -1; float v1 = -INFINITY;
#pragma unroll
        for (int e = 0; e < EE; e++) {
            if (e == i0) continue;
            if (acc[e] > v1) { v1 = acc[e]; i1 = e; }
        }
        float ex = expf(v1 - v0);
        float inv = 1.0f / (1.0f + ex);
        float w0 = inv;
        float w1 = ex * inv;

        int p0 = atomicAdd(&g_cnt[i0], 1);
        g_tok[i0][p0] = warp; g_wt[i0][p0] = w0;
        int p1 = atomicAdd(&g_cnt[i1], 1);
        g_tok[i1][p1] = warp; g_wt[i1][p1] = w1;
    }
}

// ---------------- fused gate+up tensor-core GEMM ---------------------------
// Block tile 128(M) x 64(N), BK=16. 8 warps as 4(M) x 2(N) -> warp 32x32.
// TF32 mma m16n8k8, fp32 accumulate. SiLU(gate)*up epilogue.
template <bool GATHER>
__global__ __launch_bounds__(256, 2)
void gemm_gateup(const float* __restrict__ X,
                 const float* __restrict__ Wg_all,
                 const float* __restrict__ Wu_all) {
    const int e  = GATHER ? blockIdx.z : 0;
    const int M  = GATHER ? g_cnt[e] : TT;
    const int m0 = blockIdx.y * 128;
    if (m0 >= M) return;
    const int n0 = blockIdx.x * 64;

    const float* Wg = Wg_all + (GATHER ? (size_t)e * HH * FF : 0);
    const float* Wu = Wu_all + (GATHER ? (size_t)e * HH * FF : 0);

    __shared__ uint32_t As [128][20];  // [m][k], pad 16->20 (conflict-free frag reads)
    __shared__ uint32_t Bgs[16][72];   // [k][n], pad 64->72
    __shared__ uint32_t Bus[16][72];

    const int tid  = threadIdx.x;
    const int wid  = tid >> 5, lane = tid & 31;
    const int wm   = wid >> 1, wn   = wid & 1;
    const int grp  = lane >> 2, qid = lane & 3;

    // A load mapping: 2 float4 per thread per chunk
    const int arow_l[2] = { (tid >> 2), (tid >> 2) + 64 };
    const int akq      = (tid & 3) * 4;
    const float* aptr[2];
#pragma unroll
    for (int s = 0; s < 2; s++) {
        int r = m0 + arow_l[s];
        if (r < M) {
            int tok = GATHER ? g_tok[e][r] : r;
            aptr[s] = X + (size_t)tok * HH;
        } else aptr[s] = nullptr;
    }
    // B load mapping: 1 float4 per thread per matrix per chunk
    const int bkrow = tid >> 4;
    const int bnq   = (tid & 15) * 4;

    float cg[2][4][4], cu[2][4][4];
#pragma unroll
    for (int mt = 0; mt < 2; mt++)
#pragma unroll
        for (int nt = 0; nt < 4; nt++)
#pragma unroll
            for (int i = 0; i < 4; i++) { cg[mt][nt][i] = 0.0f; cu[mt][nt][i] = 0.0f; }

    for (int kk = 0; kk < HH; kk += 16) {
#pragma unroll
        for (int s = 0; s < 2; s++)
            if (aptr[s])
                *(uint4*)&As[arow_l[s]][akq] = cvt4(*(const float4*)(aptr[s] + kk + akq));
        *(uint4*)&Bgs[bkrow][bnq] = cvt4(*(const float4*)(Wg + (size_t)(kk + bkrow) * FF + n0 + bnq));
        *(uint4*)&Bus[bkrow][bnq] = cvt4(*(const float4*)(Wu + (size_t)(kk + bkrow) * FF + n0 + bnq));
        __syncthreads();

#pragma unroll
        for (int ks = 0; ks < 16; ks += 8) {
            uint32_t a[2][4], bg[4][2], bu[4][2];
#pragma unroll
            for (int mt = 0; mt < 2; mt++) {
                int rb = wm * 32 + mt * 16 + grp;
                a[mt][0] = As[rb    ][ks + qid];
                a[mt][1] = As[rb + 8][ks + qid];
                a[mt][2] = As[rb    ][ks + qid + 4];
                a[mt][3] = As[rb + 8][ks + qid + 4];
            }
#pragma unroll
            for (int nt = 0; nt < 4; nt++) {
                int cb = wn * 32 + nt * 8 + grp;
                bg[nt][0] = Bgs[ks + qid    ][cb];
                bg[nt][1] = Bgs[ks + qid + 4][cb];
                bu[nt][0] = Bus[ks + qid    ][cb];
                bu[nt][1] = Bus[ks + qid + 4][cb];
            }
#pragma unroll
            for (int mt = 0; mt < 2; mt++)
#pragma unroll
                for (int nt = 0; nt < 4; nt++) {
                    mma8(cg[mt][nt], a[mt], bg[nt]);
                    mma8(cu[mt][nt], a[mt], bu[nt]);
                }
        }
        __syncthreads();
    }

    // epilogue: silu(g)*u, store float2 pairs
#pragma unroll
    for (int mt = 0; mt < 2; mt++) {
#pragma unroll
        for (int half = 0; half < 2; half++) {
            int m = m0 + wm * 32 + mt * 16 + grp + half * 8;
            if (m >= M) continue;
            float* orow = GATHER ? &g_act[e][m][0] : &g_sact[m][0];
#pragma unroll
            for (int nt = 0; nt < 4; nt++) {
                int c0 = n0 + wn * 32 + nt * 8 + 2 * qid;
                float g0 = cg[mt][nt][half * 2 + 0], u0 = cu[mt][nt][half * 2 + 0];
                float g1 = cg[mt][nt][half * 2 + 1], u1 = cu[mt][nt][half * 2 + 1];
                float2 o;
                o.x = (g0 / (1.0f + expf(-g0))) * u0;
                o.y = (g1 / (1.0f + expf(-g1))) * u1;
                *(float2*)&orow[c0] = o;
            }
        }
    }
}

// ---------------- down-proj tensor-core GEMM -------------------------------
// Block tile 128(M) x 128(N), BK=16. 8 warps as 4(M) x 2(N) -> warp 32x64.
template <bool EXPERT>
__global__ __launch_bounds__(256, 2)
void gemm_down(const float* __restrict__ Wd_all,
               float* __restrict__ out) {
    const int e  = EXPERT ? blockIdx.z : 0;
    const int M  = EXPERT ? g_cnt[e] : TT;
    const int m0 = blockIdx.y * 128;
    if (m0 >= M) return;
    const int n0 = blockIdx.x * 128;

    const float* Wd   = Wd_all + (EXPERT ? (size_t)e * FF * HH : 0);
    const float* Asrc = EXPERT ? &g_act[e][0][0] : &g_sact[0][0];

    __shared__ uint32_t As[128][20];
    __shared__ uint32_t Bs[16][136];   // pad 128->136

    const int tid  = threadIdx.x;
    const int wid  = tid >> 5, lane = tid & 31;
    const int wm   = wid >> 1, wn   = wid & 1;
    const int grp  = lane >> 2, qid = lane & 3;

    const int arow_l[2] = { (tid >> 2), (tid >> 2) + 64 };
    const int akq      = (tid & 3) * 4;
    const float* aptr[2];
#pragma unroll
    for (int s = 0; s < 2; s++) {
        int r = m0 + arow_l[s];
        aptr[s] = (r < M) ? (Asrc + (size_t)r * FF) : nullptr;
    }
    const int bkrow[2] = { (tid >> 5), (tid >> 5) + 8 };
    const int bnq      = (tid & 31) * 4;

    float cc[2][8][4];
#pragma unroll
    for (int mt = 0; mt < 2; mt++)
#pragma unroll
        for (int nt = 0; nt < 8; nt++)
#pragma unroll
            for (int i = 0; i < 4; i++) cc[mt][nt][i] = 0.0f;

    for (int kk = 0; kk < FF; kk += 16) {
#pragma unroll
        for (int s = 0; s < 2; s++)
            if (aptr[s])
                *(uint4*)&As[arow_l[s]][akq] = cvt4(*(const float4*)(aptr[s] + kk + akq));
#pragma unroll
        for (int s = 0; s < 2; s++)
            *(uint4*)&Bs[bkrow[s]][bnq] =
                cvt4(*(const float4*)(Wd + (size_t)(kk + bkrow[s]) * HH + n0 + bnq));
        __syncthreads();

#pragma unroll
        for (int ks = 0; ks < 16; ks += 8) {
            uint32_t a[2][4], b[8][2];
#pragma unroll
            for (int mt = 0; mt < 2; mt++) {
                int rb = wm * 32 + mt * 16 + grp;
                a[mt][0] = As[rb    ][ks + qid];
                a[mt][1] = As[rb + 8][ks + qid];
                a[mt][2] = As[rb    ][ks + qid + 4];
                a[mt][3] = As[rb + 8][ks + qid + 4];
            }
#pragma unroll
            for (int nt = 0; nt < 8; nt++) {
                int cb = wn * 64 + nt * 8 + grp;
                b[nt][0] = Bs[ks + qid    ][cb];
                b[nt][1] = Bs[ks + qid + 4][cb];
            }
#pragma unroll
            for (int mt = 0; mt < 2; mt++)
#pragma unroll
                for (int nt = 0; nt < 8; nt++)
                    mma8(cc[mt][nt], a[mt], b[nt]);
        }
        __syncthreads();
    }

#pragma unroll
    for (int mt = 0; mt < 2; mt++) {
#pragma unroll
        for (int half = 0; half < 2; half++) {
            int m = m0 + wm * 32 + mt * 16 + grp + half * 8;
            if (m >= M) continue;
            if (EXPERT) {
                int tok = g_tok[e][m];
                float w = g_wt[e][m];
                float* orow = out + (size_t)tok * HH;
#pragma unroll
                for (int nt = 0; nt < 8; nt++) {
                    int c0 = n0 + wn * 64 + nt * 8 + 2 * qid;
                    atomicAdd(&orow[c0],     w * cc[mt][nt][half * 2 + 0]);
                    atomicAdd(&orow[c0 + 1], w * cc[mt][nt][half * 2 + 1]);
                }
            } else {
                float* orow = out + (size_t)m * HH;
#pragma unroll
                for (int nt = 0; nt < 8; nt++) {
                    int c0 = n0 + wn * 64 + nt * 8 + 2 * qid;
                    float2 o = make_float2(cc[mt][nt][half * 2 + 0],
                                           cc[mt][nt][half * 2 + 1]);
                    *(float2*)&orow[c0] = o;
                }
            }
        }
    }
}

// ---------------- launch ---------------------------------------------------
extern "C" void kernel_launch(void* const* d_in, const int* in_sizes, int n_in,
                              void* d_out, int out_size) {
    const float* x   = (const float*)d_in[0];
    const float* wg  = (const float*)d_in[1];
    const float* wgp = (const float*)d_in[2];
    const float* wup = (const float*)d_in[3];
    const float* wdp = (const float*)d_in[4];
    const float* wsg = (const float*)d_in[5];
    const float* wsu = (const float*)d_in[6];
    const float* wsd = (const float*)d_in[7];
    float* out = (float*)d_out;

    int tail = out_size - TT * HH;
    int init_n = (tail > EE ? tail : EE);
    init_kernel<<<(init_n + 255) / 256, 256>>>(out, out_size);

    router_kernel<<<TT / 8, 256>>>(x, wg);

    dim3 gs1(FF / 64, TT / 128, 1);
    gemm_gateup<false><<<gs1, 256>>>(x, wsg, wsu);

    dim3 ge1(FF / 64, TT / 128, EE);
    gemm_gateup<true><<<ge1, 256>>>(x, wgp, wup);

    dim3 gs2(HH / 128, TT / 128, 1);
    gemm_down<false><<<gs2, 256>>>(wsd, out);   // plain store: initializes out

    dim3 ge2(HH / 128, TT / 128, EE);
    gemm_down<true><<<ge2, 256>>>(wdp, out);    // weighted atomicAdd combine
}

// round 4
// speedup vs baseline: 4.7003x; 1.0923x over previous
#include <cuda_runtime.h>
#include <math.h>
#include <stdint.h>

#define TT 2048
#define HH 1024
#define FF 1024
#define EE 8

// ---------------- scratch (device globals; no allocation allowed) ----------
__device__ int   g_cnt[EE];
__device__ int   g_tok[EE][TT];
__device__ float g_wt [EE][TT];
__device__ float g_act[EE][TT][FF];   // routed silu(g)*u activations (64 MB)
__device__ float g_sact[TT][FF];      // shared-expert activations (8 MB)

// ---------------- helpers ---------------------------------------------------
__device__ __forceinline__ uint32_t f2tf32(float f) {
    uint32_t u;
    asm("cvt.rna.tf32.f32 %0, %1;" : "=r"(u) : "f"(f));
    return u;
}

__device__ __forceinline__ void mma8(float* c, const uint32_t* a, const uint32_t* b) {
    asm volatile(
        "mma.sync.aligned.m16n8k8.row.col.f32.tf32.tf32.f32 "
        "{%0,%1,%2,%3}, {%4,%5,%6,%7}, {%8,%9}, {%0,%1,%2,%3};"
        : "+f"(c[0]), "+f"(c[1]), "+f"(c[2]), "+f"(c[3])
        : "r"(a[0]), "r"(a[1]), "r"(a[2]), "r"(a[3]), "r"(b[0]), "r"(b[1]));
}

__device__ __forceinline__ uint4 cvt4(float4 v) {
    return make_uint4(f2tf32(v.x), f2tf32(v.y), f2tf32(v.z), f2tf32(v.w));
}

// ---------------- init: zero counters + zero any tail (aux_loss) -----------
__global__ void init_kernel(float* __restrict__ out, int out_size) {
    int i = blockIdx.x * blockDim.x + threadIdx.x;
    if (i < EE) g_cnt[i] = 0;
    int tail = out_size - TT * HH;
    if (i < tail) out[TT * HH + i] = 0.0f;
}

// ---------------- router: logits, top-2, softmax, scatter ------------------
__global__ void router_kernel(const float* __restrict__ x,
                              const float* __restrict__ wg) {
    int warp = (blockIdx.x * blockDim.x + threadIdx.x) >> 5;
    int lane = threadIdx.x & 31;
    if (warp >= TT) return;
    const float* xr = x + (size_t)warp * HH;

    float acc[EE];
#pragma unroll
    for (int e = 0; e < EE; e++) acc[e] = 0.0f;

    for (int h = lane; h < HH; h += 32) {
        float xv = xr[h];
        const float4* w4 = (const float4*)(wg + (size_t)h * EE);
        float4 a = w4[0], b = w4[1];
        acc[0] += xv * a.x; acc[1] += xv * a.y;
        acc[2] += xv * a.z; acc[3] += xv * a.w;
        acc[4] += xv * b.x; acc[5] += xv * b.y;
        acc[6] += xv * b.z; acc[7] += xv * b.w;
    }
#pragma unroll
    for (int e = 0; e < EE; e++)
#pragma unroll
        for (int o = 16; o > 0; o >>= 1)
            acc[e] += __shfl_xor_sync(0xffffffffu, acc[e], o);

    if (lane == 0) {
        int i0 = 0; float v0 = acc[0];
#pragma unroll
        for (int e = 1; e < EE; e++) if (acc[e] > v0) { v0 = acc[e]; i0 = e; }
        int i1 = -1; float v1 = -INFINITY;
#pragma unroll
        for (int e = 0; e < EE; e++) {
            if (e == i0) continue;
            if (acc[e] > v1) { v1 = acc[e]; i1 = e; }
        }
        float ex = expf(v1 - v0);
        float inv = 1.0f / (1.0f + ex);
        float w0 = inv;
        float w1 = ex * inv;

        int p0 = atomicAdd(&g_cnt[i0], 1);
        g_tok[i0][p0] = warp; g_wt[i0][p0] = w0;
        int p1 = atomicAdd(&g_cnt[i1], 1);
        g_tok[i1][p1] = warp; g_wt[i1][p1] = w1;
    }
}

// ---------------- fused gate+up tensor-core GEMM (double-buffered) ---------
// Block tile 128(M) x 64(N), BK=16, smem ping-pong, register-staged prefetch.
// 8 warps as 4(M) x 2(N) -> warp 32x32. TF32 mma, fp32 accum, SiLU epilogue.
template <bool GATHER>
__global__ __launch_bounds__(256, 2)
void gemm_gateup(const float* __restrict__ X,
                 const float* __restrict__ Wg_all,
                 const float* __restrict__ Wu_all) {
    const int e  = GATHER ? blockIdx.z : 0;
    const int M  = GATHER ? g_cnt[e] : TT;
    const int m0 = blockIdx.y * 128;
    if (m0 >= M) return;
    const int n0 = blockIdx.x * 64;

    __shared__ uint32_t As [2][128][20];
    __shared__ uint32_t Bgs[2][16][72];
    __shared__ uint32_t Bus[2][16][72];

    const int tid  = threadIdx.x;
    const int wid  = tid >> 5, lane = tid & 31;
    const int wm   = wid >> 1, wn   = wid & 1;
    const int grp  = lane >> 2, qid = lane & 3;

    // A load mapping: 2 float4 per thread per chunk
    const int arow_l0 = tid >> 2;
    const int akq     = (tid & 3) * 4;
    const float* aptr[2];
#pragma unroll
    for (int s = 0; s < 2; s++) {
        int r = m0 + arow_l0 + s * 64;
        if (r < M) {
            int tok = GATHER ? g_tok[e][r] : r;
            aptr[s] = X + (size_t)tok * HH + akq;
        } else aptr[s] = nullptr;
    }
    // B load mapping: 1 float4 per thread per matrix per chunk
    const int bkrow = tid >> 4;
    const int bnq   = (tid & 15) * 4;
    const float* gptr = Wg_all + (GATHER ? (size_t)e * HH * FF : 0)
                        + (size_t)bkrow * FF + n0 + bnq;
    const float* uptr = Wu_all + (GATHER ? (size_t)e * HH * FF : 0)
                        + (size_t)bkrow * FF + n0 + bnq;

    float cg[2][4][4], cu[2][4][4];
#pragma unroll
    for (int mt = 0; mt < 2; mt++)
#pragma unroll
        for (int nt = 0; nt < 4; nt++)
#pragma unroll
            for (int i = 0; i < 4; i++) { cg[mt][nt][i] = 0.0f; cu[mt][nt][i] = 0.0f; }

    // prologue: chunk 0 -> stage 0
    {
        float4 av0 = aptr[0] ? *(const float4*)(aptr[0]) : make_float4(0,0,0,0);
        float4 av1 = aptr[1] ? *(const float4*)(aptr[1]) : make_float4(0,0,0,0);
        float4 gv  = *(const float4*)(gptr);
        float4 uv  = *(const float4*)(uptr);
        *(uint4*)&As[0][arow_l0     ][akq] = cvt4(av0);
        *(uint4*)&As[0][arow_l0 + 64][akq] = cvt4(av1);
        *(uint4*)&Bgs[0][bkrow][bnq] = cvt4(gv);
        *(uint4*)&Bus[0][bkrow][bnq] = cvt4(uv);
    }
    __syncthreads();

    int buf = 0;
    for (int kk = 16; kk <= HH; kk += 16) {
        const bool has_next = (kk < HH);
        float4 nav0, nav1, ngv, nuv;
        if (has_next) {
            nav0 = aptr[0] ? *(const float4*)(aptr[0] + kk) : make_float4(0,0,0,0);
            nav1 = aptr[1] ? *(const float4*)(aptr[1] + kk) : make_float4(0,0,0,0);
            ngv  = *(const float4*)(gptr + (size_t)kk * FF);
            nuv  = *(const float4*)(uptr + (size_t)kk * FF);
        }

#pragma unroll
        for (int ks = 0; ks < 16; ks += 8) {
            uint32_t a[2][4], bg[4][2], bu[4][2];
#pragma unroll
            for (int mt = 0; mt < 2; mt++) {
                int rb = wm * 32 + mt * 16 + grp;
                a[mt][0] = As[buf][rb    ][ks + qid];
                a[mt][1] = As[buf][rb + 8][ks + qid];
                a[mt][2] = As[buf][rb    ][ks + qid + 4];
                a[mt][3] = As[buf][rb + 8][ks + qid + 4];
            }
#pragma unroll
            for (int nt = 0; nt < 4; nt++) {
                int cb = wn * 32 + nt * 8 + grp;
                bg[nt][0] = Bgs[buf][ks + qid    ][cb];
                bg[nt][1] = Bgs[buf][ks + qid + 4][cb];
                bu[nt][0] = Bus[buf][ks + qid    ][cb];
                bu[nt][1] = Bus[buf][ks + qid + 4][cb];
            }
#pragma unroll
            for (int mt = 0; mt < 2; mt++)
#pragma unroll
                for (int nt = 0; nt < 4; nt++) {
                    mma8(cg[mt][nt], a[mt], bg[nt]);
                    mma8(cu[mt][nt], a[mt], bu[nt]);
                }
        }

        if (has_next) {
            int nb = buf ^ 1;
            *(uint4*)&As[nb][arow_l0     ][akq] = cvt4(nav0);
            *(uint4*)&As[nb][arow_l0 + 64][akq] = cvt4(nav1);
            *(uint4*)&Bgs[nb][bkrow][bnq] = cvt4(ngv);
            *(uint4*)&Bus[nb][bkrow][bnq] = cvt4(nuv);
            __syncthreads();
            buf = nb;
        }
    }

    // epilogue: silu(g)*u, store float2 pairs
#pragma unroll
    for (int mt = 0; mt < 2; mt++) {
#pragma unroll
        for (int half = 0; half < 2; half++) {
            int m = m0 + wm * 32 + mt * 16 + grp + half * 8;
            if (m >= M) continue;
            float* orow = GATHER ? &g_act[e][m][0] : &g_sact[m][0];
#pragma unroll
            for (int nt = 0; nt < 4; nt++) {
                int c0 = n0 + wn * 32 + nt * 8 + 2 * qid;
                float g0 = cg[mt][nt][half * 2 + 0], u0 = cu[mt][nt][half * 2 + 0];
                float g1 = cg[mt][nt][half * 2 + 1], u1 = cu[mt][nt][half * 2 + 1];
                float2 o;
                o.x = (g0 / (1.0f + expf(-g0))) * u0;
                o.y = (g1 / (1.0f + expf(-g1))) * u1;
                *(float2*)&orow[c0] = o;
            }
        }
    }
}

// ---------------- down-proj tensor-core GEMM (double-buffered) -------------
// Block tile 128(M) x 128(N), BK=16, smem ping-pong, register prefetch.
template <bool EXPERT>
__global__ __launch_bounds__(256, 2)
void gemm_down(const float* __restrict__ Wd_all,
               float* __restrict__ out) {
    const int e  = EXPERT ? blockIdx.z : 0;
    const int M  = EXPERT ? g_cnt[e] : TT;
    const int m0 = blockIdx.y * 128;
    if (m0 >= M) return;
    const int n0 = blockIdx.x * 128;

    const float* Asrc = EXPERT ? &g_act[e][0][0] : &g_sact[0][0];

    __shared__ uint32_t As[2][128][20];
    __shared__ uint32_t Bs[2][16][136];

    const int tid  = threadIdx.x;
    const int wid  = tid >> 5, lane = tid & 31;
    const int wm   = wid >> 1, wn   = wid & 1;
    const int grp  = lane >> 2, qid = lane & 3;

    const int arow_l0 = tid >> 2;
    const int akq     = (tid & 3) * 4;
    const float* aptr[2];
#pragma unroll
    for (int s = 0; s < 2; s++) {
        int r = m0 + arow_l0 + s * 64;
        aptr[s] = (r < M) ? (Asrc + (size_t)r * FF + akq) : nullptr;
    }
    const int bkrow0 = tid >> 5;
    const int bnq    = (tid & 31) * 4;
    const float* wptr = Wd_all + (EXPERT ? (size_t)e * FF * HH : 0)
                        + (size_t)bkrow0 * HH + n0 + bnq;

    float cc[2][8][4];
#pragma unroll
    for (int mt = 0; mt < 2; mt++)
#pragma unroll
        for (int nt = 0; nt < 8; nt++)
#pragma unroll
            for (int i = 0; i < 4; i++) cc[mt][nt][i] = 0.0f;

    // prologue
    {
        float4 av0 = aptr[0] ? *(const float4*)(aptr[0]) : make_float4(0,0,0,0);
        float4 av1 = aptr[1] ? *(const float4*)(aptr[1]) : make_float4(0,0,0,0);
        float4 bv0 = *(const float4*)(wptr);
        float4 bv1 = *(const float4*)(wptr + (size_t)8 * HH);
        *(uint4*)&As[0][arow_l0     ][akq] = cvt4(av0);
        *(uint4*)&As[0][arow_l0 + 64][akq] = cvt4(av1);
        *(uint4*)&Bs[0][bkrow0    ][bnq] = cvt4(bv0);
        *(uint4*)&Bs[0][bkrow0 + 8][bnq] = cvt4(bv1);
    }
    __syncthreads();

    int buf = 0;
    for (int kk = 16; kk <= FF; kk += 16) {
        const bool has_next = (kk < FF);
        float4 nav0, nav1, nbv0, nbv1;
        if (has_next) {
            nav0 = aptr[0] ? *(const float4*)(aptr[0] + kk) : make_float4(0,0,0,0);
            nav1 = aptr[1] ? *(const float4*)(aptr[1] + kk) : make_float4(0,0,0,0);
            nbv0 = *(const float4*)(wptr + (size_t)kk * HH);
            nbv1 = *(const float4*)(wptr + (size_t)(kk + 8) * HH);
        }

#pragma unroll
        for (int ks = 0; ks < 16; ks += 8) {
            uint32_t a[2][4], b[8][2];
#pragma unroll
            for (int mt = 0; mt < 2; mt++) {
                int rb = wm * 32 + mt * 16 + grp;
                a[mt][0] = As[buf][rb    ][ks + qid];
                a[mt][1] = As[buf][rb + 8][ks + qid];
                a[mt][2] = As[buf][rb    ][ks + qid + 4];
                a[mt][3] = As[buf][rb + 8][ks + qid + 4];
            }
#pragma unroll
            for (int nt = 0; nt < 8; nt++) {
                int cb = wn * 64 + nt * 8 + grp;
                b[nt][0] = Bs[buf][ks + qid    ][cb];
                b[nt][1] = Bs[buf][ks + qid + 4][cb];
            }
#pragma unroll
            for (int mt = 0; mt < 2; mt++)
#pragma unroll
                for (int nt = 0; nt < 8; nt++)
                    mma8(cc[mt][nt], a[mt], b[nt]);
        }

        if (has_next) {
            int nb = buf ^ 1;
            *(uint4*)&As[nb][arow_l0     ][akq] = cvt4(nav0);
            *(uint4*)&As[nb][arow_l0 + 64][akq] = cvt4(nav1);
            *(uint4*)&Bs[nb][bkrow0    ][bnq] = cvt4(nbv0);
            *(uint4*)&Bs[nb][bkrow0 + 8][bnq] = cvt4(nbv1);
            __syncthreads();
            buf = nb;
        }
    }

#pragma unroll
    for (int mt = 0; mt < 2; mt++) {
#pragma unroll
        for (int half = 0; half < 2; half++) {
            int m = m0 + wm * 32 + mt * 16 + grp + half * 8;
            if (m >= M) continue;
            if (EXPERT) {
                int tok = g_tok[e][m];
                float w = g_wt[e][m];
                float* orow = out + (size_t)tok * HH;
#pragma unroll
                for (int nt = 0; nt < 8; nt++) {
                    int c0 = n0 + wn * 64 + nt * 8 + 2 * qid;
                    atomicAdd(&orow[c0],     w * cc[mt][nt][half * 2 + 0]);
                    atomicAdd(&orow[c0 + 1], w * cc[mt][nt][half * 2 + 1]);
                }
            } else {
                float* orow = out + (size_t)m * HH;
#pragma unroll
                for (int nt = 0; nt < 8; nt++) {
                    int c0 = n0 + wn * 64 + nt * 8 + 2 * qid;
                    float2 o = make_float2(cc[mt][nt][half * 2 + 0],
                                           cc[mt][nt][half * 2 + 1]);
                    *(float2*)&orow[c0] = o;
                }
            }
        }
    }
}

// ---------------- launch ---------------------------------------------------
extern "C" void kernel_launch(void* const* d_in, const int* in_sizes, int n_in,
                              void* d_out, int out_size) {
    const float* x   = (const float*)d_in[0];
    const float* wg  = (const float*)d_in[1];
    const float* wgp = (const float*)d_in[2];
    const float* wup = (const float*)d_in[3];
    const float* wdp = (const float*)d_in[4];
    const float* wsg = (const float*)d_in[5];
    const float* wsu = (const float*)d_in[6];
    const float* wsd = (const float*)d_in[7];
    float* out = (float*)d_out;

    int tail = out_size - TT * HH;
    int init_n = (tail > EE ? tail : EE);
    init_kernel<<<(init_n + 255) / 256, 256>>>(out, out_size);

    router_kernel<<<TT / 8, 256>>>(x, wg);

    dim3 gs1(FF / 64, TT / 128, 1);
    gemm_gateup<false><<<gs1, 256>>>(x, wsg, wsu);

    dim3 ge1(FF / 64, TT / 128, EE);
    gemm_gateup<true><<<ge1, 256>>>(x, wgp, wup);

    dim3 gs2(HH / 128, TT / 128, 1);
    gemm_down<false><<<gs2, 256>>>(wsd, out);   // plain store: initializes out

    dim3 ge2(HH / 128, TT / 128, EE);
    gemm_down<true><<<ge2, 256>>>(wdp, out);    // weighted atomicAdd combine
}

// round 7
// speedup vs baseline: 4.8641x; 1.0348x over previous
#include <cuda_runtime.h>
#include <math.h>
#include <stdint.h>

#define TT 2048
#define HH 1024
#define FF 1024
#define EE 8

// ---------------- scratch (device globals; no allocation allowed) ----------
__device__ int   g_cnt[EE];
__device__ int   g_tok[EE][TT];
__device__ float g_wt [EE][TT];
__device__ float g_act[EE][TT][FF];   // routed silu(g)*u activations (64 MB)
__device__ float g_sact[TT][FF];      // shared-expert activations (8 MB)

// ---------------- helpers ---------------------------------------------------
__device__ __forceinline__ uint32_t f2tf32(float f) {
    uint32_t u;
    asm("cvt.rna.tf32.f32 %0, %1;" : "=r"(u) : "f"(f));
    return u;
}
__device__ __forceinline__ uint4 cvt4(float4 v) {
    return make_uint4(f2tf32(v.x), f2tf32(v.y), f2tf32(v.z), f2tf32(v.w));
}
__device__ __forceinline__ uint32_t smem_u32(const void* p) {
    uint32_t a;
    asm("{ .reg .u64 t; cvta.to.shared.u64 t, %1; cvt.u32.u64 %0, t; }"
        : "=r"(a) : "l"(p));
    return a;
}
__device__ __forceinline__ void mma8(float* c, const uint32_t* a, const uint32_t* b) {
    asm volatile(
        "mma.sync.aligned.m16n8k8.row.col.f32.tf32.tf32.f32 "
        "{%0,%1,%2,%3}, {%4,%5,%6,%7}, {%8,%9}, {%0,%1,%2,%3};"
        : "+f"(c[0]), "+f"(c[1]), "+f"(c[2]), "+f"(c[3])
        : "r"(a[0]), "r"(a[1]), "r"(a[2]), "r"(a[3]), "r"(b[0]), "r"(b[1]));
}
__device__ __forceinline__ void ldsm4(uint32_t* r, uint32_t addr) {
    asm volatile("ldmatrix.sync.aligned.m8n8.x4.shared.b16 {%0,%1,%2,%3}, [%4];"
        : "=r"(r[0]), "=r"(r[1]), "=r"(r[2]), "=r"(r[3]) : "r"(addr));
}

// padded row length (floats): 36 floats = 144B -> LDSM/STS conflict-free
#define LDR 36

// gateup smem layout (bytes): A 2x18432 | Bg 2x9216 | Bu 2x9216 = 73728
#define GU_A    0
#define GU_AS   18432
#define GU_BG   36864
#define GU_BGS  9216
#define GU_BU   55296
#define GU_BUS  9216
#define GU_BYTES 73728
// down smem layout: A 2x18432 | B 2x18432 = 73728
#define DN_A    0
#define DN_AS   18432
#define DN_B    36864
#define DN_BS   18432
#define DN_BYTES 73728

// ---------------- init ------------------------------------------------------
__global__ void init_kernel(float* __restrict__ out, int out_size) {
    int i = blockIdx.x * blockDim.x + threadIdx.x;
    if (i < EE) g_cnt[i] = 0;
    int tail = out_size - TT * HH;
    if (i < tail) out[TT * HH + i] = 0.0f;
}

// ---------------- router ----------------------------------------------------
__global__ void router_kernel(const float* __restrict__ x,
                              const float* __restrict__ wg) {
    int warp = (blockIdx.x * blockDim.x + threadIdx.x) >> 5;
    int lane = threadIdx.x & 31;
    if (warp >= TT) return;
    const float* xr = x + (size_t)warp * HH;

    float acc[EE];
#pragma unroll
    for (int e = 0; e < EE; e++) acc[e] = 0.0f;
    for (int h = lane; h < HH; h += 32) {
        float xv = xr[h];
        const float4* w4 = (const float4*)(wg + (size_t)h * EE);
        float4 a = w4[0], b = w4[1];
        acc[0] += xv * a.x; acc[1] += xv * a.y;
        acc[2] += xv * a.z; acc[3] += xv * a.w;
        acc[4] += xv * b.x; acc[5] += xv * b.y;
        acc[6] += xv * b.z; acc[7] += xv * b.w;
    }
#pragma unroll
    for (int e = 0; e < EE; e++)
#pragma unroll
        for (int o = 16; o > 0; o >>= 1)
            acc[e] += __shfl_xor_sync(0xffffffffu, acc[e], o);

    if (lane == 0) {
        int i0 = 0; float v0 = acc[0];
#pragma unroll
        for (int e = 1; e < EE; e++) if (acc[e] > v0) { v0 = acc[e]; i0 = e; }
        int i1 = -1; float v1 = -INFINITY;
#pragma unroll
        for (int e = 0; e < EE; e++) {
            if (e == i0) continue;
            if (acc[e] > v1) { v1 = acc[e]; i1 = e; }
        }
        float ex = expf(v1 - v0);
        float inv = 1.0f / (1.0f + ex);
        int p0 = atomicAdd(&g_cnt[i0], 1);
        g_tok[i0][p0] = warp; g_wt[i0][p0] = inv;
        int p1 = atomicAdd(&g_cnt[i1], 1);
        g_tok[i1][p1] = warp; g_wt[i1][p1] = ex * inv;
    }
}

// ---------------- fused gate+up GEMM (TF32 mma + LDSM, BK=32) --------------
// Block tile 128(M) x 64(N). 8 warps as 4(M) x 2(N) -> warp 32x32.
// A smem: [m][k] rows (LDR pad). B smem: [n][k] rows (transposed load).
template <bool GATHER>
__global__ __launch_bounds__(256, 2)
void gemm_gateup(const float* __restrict__ X,
                 const float* __restrict__ Wg_all,
                 const float* __restrict__ Wu_all) {
    const int e  = GATHER ? blockIdx.z : 0;
    const int M  = GATHER ? g_cnt[e] : TT;
    const int m0 = blockIdx.y * 128;
    if (m0 >= M) return;
    const int n0 = blockIdx.x * 64;

    extern __shared__ char smem[];
    const uint32_t sbase = smem_u32(smem);
    const int tid  = threadIdx.x;
    const int wid  = tid >> 5, lane = tid & 31;
    const int wm   = wid >> 1, wn   = wid & 1;
    const int grp  = lane >> 2, qid = lane & 3;

    // ---- producers ----
    // A: row per thread-pair, 16 floats each
    const int arow = tid >> 1;
    const int ako  = (tid & 1) * 16;
    const float* aSrc = nullptr;
    if (m0 + arow < M) {
        int tok = GATHER ? g_tok[e][m0 + arow] : (m0 + arow);
        aSrc = X + (size_t)tok * HH + ako;
    }
    // B transposed gather: thread handles (n = n_t, k = ktB..ktB+7)
    const int n_t = tid >> 2;
    const int ktB = (tid & 3) * 8;
    const float* gp = Wg_all + (GATHER ? (size_t)e * HH * FF : 0)
                      + (size_t)ktB * FF + n0 + n_t;
    const float* up = Wu_all + (GATHER ? (size_t)e * HH * FF : 0)
                      + (size_t)ktB * FF + n0 + n_t;

    // ---- LDSM per-lane byte offsets (within a stage) ----
    uint32_t aoff[2], boff[2];
#pragma unroll
    for (int mt = 0; mt < 2; mt++)
        aoff[mt] = ((wm * 32 + mt * 16 + (lane & 15)) * LDR + ((lane & 16) ? 4 : 0)) * 4;
#pragma unroll
    for (int p = 0; p < 2; p++)
        boff[p] = ((wn * 32 + p * 16 + (lane & 7) + ((lane & 16) ? 8 : 0)) * LDR
                   + ((lane & 8) ? 4 : 0)) * 4;

    float cg[2][4][4], cu[2][4][4];
#pragma unroll
    for (int mt = 0; mt < 2; mt++)
#pragma unroll
        for (int nt = 0; nt < 4; nt++)
#pragma unroll
            for (int i = 0; i < 4; i++) { cg[mt][nt][i] = 0.0f; cu[mt][nt][i] = 0.0f; }

    // ---- store helper targets ----
    auto storeChunk = [&](int s, const float4* av, const float* bgv, const float* buv) {
        float* Arow = (float*)(smem + GU_A + s * GU_AS) + arow * LDR + ako;
#pragma unroll
        for (int i = 0; i < 4; i++)
            *(uint4*)(Arow + 4 * i) = cvt4(av[i]);
        float* Grow = (float*)(smem + GU_BG + s * GU_BGS) + n_t * LDR + ktB;
        float* Urow = (float*)(smem + GU_BU + s * GU_BUS) + n_t * LDR + ktB;
#pragma unroll
        for (int i = 0; i < 2; i++) {
            uint4 vg = make_uint4(f2tf32(bgv[4*i]), f2tf32(bgv[4*i+1]),
                                  f2tf32(bgv[4*i+2]), f2tf32(bgv[4*i+3]));
            uint4 vu = make_uint4(f2tf32(buv[4*i]), f2tf32(buv[4*i+1]),
                                  f2tf32(buv[4*i+2]), f2tf32(buv[4*i+3]));
            *(uint4*)(Grow + 4 * i) = vg;
            *(uint4*)(Urow + 4 * i) = vu;
        }
    };

    // prologue: chunk 0 -> stage 0
    {
        float4 av[4];
        float bgv[8], buv[8];
#pragma unroll
        for (int i = 0; i < 4; i++)
            av[i] = aSrc ? *(const float4*)(aSrc + 4 * i) : make_float4(0, 0, 0, 0);
#pragma unroll
        for (int j = 0; j < 8; j++) {
            bgv[j] = gp[(size_t)j * FF];
            buv[j] = up[(size_t)j * FF];
        }
        storeChunk(0, av, bgv, buv);
    }
    __syncthreads();

    int buf = 0;
    for (int c = 0; c < 32; c++) {
        const int kk = (c + 1) * 32;
        const bool has_next = (kk < HH);
        float4 av[4];
        float bgv[8], buv[8];
        if (has_next) {
#pragma unroll
            for (int i = 0; i < 4; i++)
                av[i] = aSrc ? *(const float4*)(aSrc + kk + 4 * i) : make_float4(0, 0, 0, 0);
#pragma unroll
            for (int j = 0; j < 8; j++) {
                bgv[j] = gp[(size_t)(kk + j) * FF];
                buv[j] = up[(size_t)(kk + j) * FF];
            }
        }

        const uint32_t Ab = sbase + GU_A  + buf * GU_AS;
        const uint32_t Gb = sbase + GU_BG + buf * GU_BGS;
        const uint32_t Ub = sbase + GU_BU + buf * GU_BUS;
#pragma unroll
        for (int ks = 0; ks < 32; ks += 8) {
            uint32_t a[2][4], bg_[8], bu_[8];
            ldsm4(a[0], Ab + aoff[0] + ks * 4);
            ldsm4(a[1], Ab + aoff[1] + ks * 4);
            ldsm4(&bg_[0], Gb + boff[0] + ks * 4);
            ldsm4(&bg_[4], Gb + boff[1] + ks * 4);
            ldsm4(&bu_[0], Ub + boff[0] + ks * 4);
            ldsm4(&bu_[4], Ub + boff[1] + ks * 4);
#pragma unroll
            for (int mt = 0; mt < 2; mt++)
#pragma unroll
                for (int nt = 0; nt < 4; nt++) {
                    mma8(cg[mt][nt], a[mt], &bg_[nt * 2]);
                    mma8(cu[mt][nt], a[mt], &bu_[nt * 2]);
                }
        }

        if (has_next) {
            storeChunk(buf ^ 1, av, bgv, buv);
            __syncthreads();
            buf ^= 1;
        }
    }

    // epilogue: silu(g)*u
#pragma unroll
    for (int mt = 0; mt < 2; mt++) {
#pragma unroll
        for (int half = 0; half < 2; half++) {
            int m = m0 + wm * 32 + mt * 16 + grp + half * 8;
            if (m >= M) continue;
            float* orow = GATHER ? &g_act[e][m][0] : &g_sact[m][0];
#pragma unroll
            for (int nt = 0; nt < 4; nt++) {
                int c0 = n0 + wn * 32 + nt * 8 + 2 * qid;
                float g0 = cg[mt][nt][half * 2 + 0], u0 = cu[mt][nt][half * 2 + 0];
                float g1 = cg[mt][nt][half * 2 + 1], u1 = cu[mt][nt][half * 2 + 1];
                float2 o;
                o.x = (g0 / (1.0f + expf(-g0))) * u0;
                o.y = (g1 / (1.0f + expf(-g1))) * u1;
                *(float2*)&orow[c0] = o;
            }
        }
    }
}

// ---------------- down-proj GEMM (TF32 mma + LDSM, BK=32) ------------------
// Block tile 128(M) x 128(N). 8 warps as 4(M) x 2(N) -> warp 32x64.
template <bool EXPERT>
__global__ __launch_bounds__(256, 2)
void gemm_down(const float* __restrict__ Wd_all,
               float* __restrict__ out) {
    const int e  = EXPERT ? blockIdx.z : 0;
    const int M  = EXPERT ? g_cnt[e] : TT;
    const int m0 = blockIdx.y * 128;
    if (m0 >= M) return;
    const int n0 = blockIdx.x * 128;

    extern __shared__ char smem[];
    const uint32_t sbase = smem_u32(smem);
    const int tid  = threadIdx.x;
    const int wid  = tid >> 5, lane = tid & 31;
    const int wm   = wid >> 1, wn   = wid & 1;
    const int grp  = lane >> 2, qid = lane & 3;

    const float* Asrc = EXPERT ? &g_act[e][0][0] : &g_sact[0][0];

    const int arow = tid >> 1;
    const int ako  = (tid & 1) * 16;
    const float* aSrc = (m0 + arow < M) ? (Asrc + (size_t)(m0 + arow) * FF + ako) : nullptr;

    // B transposed gather: thread handles (n = n_t, k = ktB..ktB+15)
    const int n_t = tid >> 1;
    const int ktB = (tid & 1) * 16;
    const float* wp = Wd_all + (EXPERT ? (size_t)e * FF * HH : 0)
                      + (size_t)ktB * HH + n0 + n_t;

    uint32_t aoff[2], boff[4];
#pragma unroll
    for (int mt = 0; mt < 2; mt++)
        aoff[mt] = ((wm * 32 + mt * 16 + (lane & 15)) * LDR + ((lane & 16) ? 4 : 0)) * 4;
#pragma unroll
    for (int p = 0; p < 4; p++)
        boff[p] = ((wn * 64 + p * 16 + (lane & 7) + ((lane & 16) ? 8 : 0)) * LDR
                   + ((lane & 8) ? 4 : 0)) * 4;

    float cc[2][8][4];
#pragma unroll
    for (int mt = 0; mt < 2; mt++)
#pragma unroll
        for (int nt = 0; nt < 8; nt++)
#pragma unroll
            for (int i = 0; i < 4; i++) cc[mt][nt][i] = 0.0f;

    auto storeChunk = [&](int s, const float4* av, const float* bv) {
        float* Arow = (float*)(smem + DN_A + s * DN_AS) + arow * LDR + ako;
#pragma unroll
        for (int i = 0; i < 4; i++)
            *(uint4*)(Arow + 4 * i) = cvt4(av[i]);
        float* Brow = (float*)(smem + DN_B + s * DN_BS) + n_t * LDR + ktB;
#pragma unroll
        for (int i = 0; i < 4; i++) {
            uint4 v = make_uint4(f2tf32(bv[4*i]), f2tf32(bv[4*i+1]),
                                 f2tf32(bv[4*i+2]), f2tf32(bv[4*i+3]));
            *(uint4*)(Brow + 4 * i) = v;
        }
    };

    // prologue
    {
        float4 av[4];
        float bv[16];
#pragma unroll
        for (int i = 0; i < 4; i++)
            av[i] = aSrc ? *(const float4*)(aSrc + 4 * i) : make_float4(0, 0, 0, 0);
#pragma unroll
        for (int j = 0; j < 16; j++)
            bv[j] = wp[(size_t)j * HH];
        storeChunk(0, av, bv);
    }
    __syncthreads();

    int buf = 0;
    for (int c = 0; c < 32; c++) {
        const int kk = (c + 1) * 32;
        const bool has_next = (kk < FF);
        float4 av[4];
        float bv[16];
        if (has_next) {
#pragma unroll
            for (int i = 0; i < 4; i++)
                av[i] = aSrc ? *(const float4*)(aSrc + kk + 4 * i) : make_float4(0, 0, 0, 0);
#pragma unroll
            for (int j = 0; j < 16; j++)
                bv[j] = wp[(size_t)(kk + j) * HH];
        }

        const uint32_t Ab = sbase + DN_A + buf * DN_AS;
        const uint32_t Bb = sbase + DN_B + buf * DN_BS;
#pragma unroll
        for (int ks = 0; ks < 32; ks += 8) {
            uint32_t a[2][4], b_[16];
            ldsm4(a[0], Ab + aoff[0] + ks * 4);
            ldsm4(a[1], Ab + aoff[1] + ks * 4);
#pragma unroll
            for (int p = 0; p < 4; p++)
                ldsm4(&b_[4 * p], Bb + boff[p] + ks * 4);
#pragma unroll
            for (int mt = 0; mt < 2; mt++)
#pragma unroll
                for (int nt = 0; nt < 8; nt++)
                    mma8(cc[mt][nt], a[mt], &b_[nt * 2]);
        }

        if (has_next) {
            storeChunk(buf ^ 1, av, bv);
            __syncthreads();
            buf ^= 1;
        }
    }

#pragma unroll
    for (int mt = 0; mt < 2; mt++) {
#pragma unroll
        for (int half = 0; half < 2; half++) {
            int m = m0 + wm * 32 + mt * 16 + grp + half * 8;
            if (m >= M) continue;
            if (EXPERT) {
                int tok = g_tok[e][m];
                float w = g_wt[e][m];
                float* orow = out + (size_t)tok * HH;
#pragma unroll
                for (int nt = 0; nt < 8; nt++) {
                    int c0 = n0 + wn * 64 + nt * 8 + 2 * qid;
                    atomicAdd(&orow[c0],     w * cc[mt][nt][half * 2 + 0]);
                    atomicAdd(&orow[c0 + 1], w * cc[mt][nt][half * 2 + 1]);
                }
            } else {
                float* orow = out + (size_t)m * HH;
#pragma unroll
                for (int nt = 0; nt < 8; nt++) {
                    int c0 = n0 + wn * 64 + nt * 8 + 2 * qid;
                    float2 o = make_float2(cc[mt][nt][half * 2 + 0],
                                           cc[mt][nt][half * 2 + 1]);
                    *(float2*)&orow[c0] = o;
                }
            }
        }
    }
}

// ---------------- launch ---------------------------------------------------
extern "C" void kernel_launch(void* const* d_in, const int* in_sizes, int n_in,
                              void* d_out, int out_size) {
    const float* x   = (const float*)d_in[0];
    const float* wg  = (const float*)d_in[1];
    const float* wgp = (const float*)d_in[2];
    const float* wup = (const float*)d_in[3];
    const float* wdp = (const float*)d_in[4];
    const float* wsg = (const float*)d_in[5];
    const float* wsu = (const float*)d_in[6];
    const float* wsd = (const float*)d_in[7];
    float* out = (float*)d_out;

    cudaFuncSetAttribute(gemm_gateup<false>, cudaFuncAttributeMaxDynamicSharedMemorySize, GU_BYTES);
    cudaFuncSetAttribute(gemm_gateup<true>,  cudaFuncAttributeMaxDynamicSharedMemorySize, GU_BYTES);
    cudaFuncSetAttribute(gemm_down<false>,   cudaFuncAttributeMaxDynamicSharedMemorySize, DN_BYTES);
    cudaFuncSetAttribute(gemm_down<true>,    cudaFuncAttributeMaxDynamicSharedMemorySize, DN_BYTES);

    int tail = out_size - TT * HH;
    int init_n = (tail > EE ? tail : EE);
    init_kernel<<<(init_n + 255) / 256, 256>>>(out, out_size);

    router_kernel<<<TT / 8, 256>>>(x, wg);

    dim3 gs1(FF / 64, TT / 128, 1);
    gemm_gateup<false><<<gs1, 256, GU_BYTES>>>(x, wsg, wsu);

    dim3 ge1(FF / 64, TT / 128, EE);
    gemm_gateup<true><<<ge1, 256, GU_BYTES>>>(x, wgp, wup);

    dim3 gs2(HH / 128, TT / 128, 1);
    gemm_down<false><<<gs2, 256, DN_BYTES>>>(wsd, out);   // plain store: initializes out

    dim3 ge2(HH / 128, TT / 128, EE);
    gemm_down<true><<<ge2, 256, DN_BYTES>>>(wdp, out);    // weighted atomicAdd combine
}

// round 8
// speedup vs baseline: 5.2881x; 1.0872x over previous
#include <cuda_runtime.h>
#include <math.h>
#include <stdint.h>

#define TT 2048
#define HH 1024
#define FF 1024
#define EE 8

// ---------------- scratch (device globals; no allocation allowed) ----------
__device__ int   g_cnt[EE];
__device__ int   g_tok[EE][TT];
__device__ float g_wt [EE][TT];
__device__ float g_act[EE][TT][FF];   // routed silu(g)*u activations (64 MB)
__device__ float g_sact[TT][FF];      // shared-expert activations (8 MB)

// ---------------- helpers ---------------------------------------------------
__device__ __forceinline__ uint32_t f2tf32(float f) {
    uint32_t u;
    asm("cvt.rna.tf32.f32 %0, %1;" : "=r"(u) : "f"(f));
    return u;
}
__device__ __forceinline__ uint4 cvt4(float4 v) {
    return make_uint4(f2tf32(v.x), f2tf32(v.y), f2tf32(v.z), f2tf32(v.w));
}
__device__ __forceinline__ uint32_t smem_u32(const void* p) {
    uint32_t a;
    asm("{ .reg .u64 t; cvta.to.shared.u64 t, %1; cvt.u32.u64 %0, t; }"
        : "=r"(a) : "l"(p));
    return a;
}
__device__ __forceinline__ void mma8(float* c, const uint32_t* a, const uint32_t* b) {
    asm volatile(
        "mma.sync.aligned.m16n8k8.row.col.f32.tf32.tf32.f32 "
        "{%0,%1,%2,%3}, {%4,%5,%6,%7}, {%8,%9}, {%0,%1,%2,%3};"
        : "+f"(c[0]), "+f"(c[1]), "+f"(c[2]), "+f"(c[3])
        : "r"(a[0]), "r"(a[1]), "r"(a[2]), "r"(a[3]), "r"(b[0]), "r"(b[1]));
}
__device__ __forceinline__ void ldsm4(uint32_t* r, uint32_t addr) {
    asm volatile("ldmatrix.sync.aligned.m8n8.x4.shared.b16 {%0,%1,%2,%3}, [%4];"
        : "=r"(r[0]), "=r"(r[1]), "=r"(r[2]), "=r"(r[3]) : "r"(addr));
}
__device__ __forceinline__ void mbar_init(uint32_t a, uint32_t cnt) {
    asm volatile("mbarrier.init.shared.b64 [%0], %1;" :: "r"(a), "r"(cnt) : "memory");
}
__device__ __forceinline__ void mbar_arrive(uint32_t a) {
    asm volatile("mbarrier.arrive.shared.b64 _, [%0];" :: "r"(a) : "memory");
}
__device__ __forceinline__ void mbar_wait(uint32_t a, uint32_t parity) {
    uint32_t done;
    asm volatile("{\n\t.reg .pred p;\n\t"
                 "mbarrier.try_wait.parity.acquire.cta.shared::cta.b64 p, [%1], %2;\n\t"
                 "selp.b32 %0, 1, 0, p;\n\t}"
                 : "=r"(done) : "r"(a), "r"(parity) : "memory");
    if (!done) {
        asm volatile("{\n\t.reg .pred P1;\n\t"
                     "WL_%=:\n\t"
                     "mbarrier.try_wait.parity.acquire.cta.shared::cta.b64 P1, [%0], %1, 0x989680;\n\t"
                     "@P1 bra.uni WD_%=;\n\t"
                     "bra.uni WL_%=;\n\t"
                     "WD_%=:\n\t}"
                     :: "r"(a), "r"(parity) : "memory");
    }
}

// A rows padded to 36 floats (144B) -> LDSM/STS conflict-free.
#define LDR 36
// gateup stage: A 128x36x4=18432 | Bg 32x72x4=9216 | Bu 9216 -> 36864
#define GU_STAGE 36864
#define GU_BG    18432
#define GU_BU    27648
#define GU_MBAR  110592   // full[3] @ +0, empty[3] @ +24
#define GU_BYTES 110656
// down stage: A 18432 | B 32x136x4=17408 -> 35840
#define DN_STAGE 35840
#define DN_B     18432
#define DN_MBAR  107520
#define DN_BYTES 107584

// ---------------- init ------------------------------------------------------
__global__ void init_kernel(float* __restrict__ out, int out_size) {
    int i = blockIdx.x * blockDim.x + threadIdx.x;
    if (i < EE) g_cnt[i] = 0;
    int tail = out_size - TT * HH;
    if (i < tail) out[TT * HH + i] = 0.0f;
}

// ---------------- router ----------------------------------------------------
__global__ void router_kernel(const float* __restrict__ x,
                              const float* __restrict__ wg) {
    int warp = (blockIdx.x * blockDim.x + threadIdx.x) >> 5;
    int lane = threadIdx.x & 31;
    if (warp >= TT) return;
    const float* xr = x + (size_t)warp * HH;

    float acc[EE];
#pragma unroll
    for (int e = 0; e < EE; e++) acc[e] = 0.0f;
    for (int h = lane; h < HH; h += 32) {
        float xv = xr[h];
        const float4* w4 = (const float4*)(wg + (size_t)h * EE);
        float4 a = w4[0], b = w4[1];
        acc[0] += xv * a.x; acc[1] += xv * a.y;
        acc[2] += xv * a.z; acc[3] += xv * a.w;
        acc[4] += xv * b.x; acc[5] += xv * b.y;
        acc[6] += xv * b.z; acc[7] += xv * b.w;
    }
#pragma unroll
    for (int e = 0; e < EE; e++)
#pragma unroll
        for (int o = 16; o > 0; o >>= 1)
            acc[e] += __shfl_xor_sync(0xffffffffu, acc[e], o);

    if (lane == 0) {
        int i0 = 0; float v0 = acc[0];
#pragma unroll
        for (int e = 1; e < EE; e++) if (acc[e] > v0) { v0 = acc[e]; i0 = e; }
        int i1 = -1; float v1 = -INFINITY;
#pragma unroll
        for (int e = 0; e < EE; e++) {
            if (e == i0) continue;
            if (acc[e] > v1) { v1 = acc[e]; i1 = e; }
        }
        float ex = expf(v1 - v0);
        float inv = 1.0f / (1.0f + ex);
        int p0 = atomicAdd(&g_cnt[i0], 1);
        g_tok[i0][p0] = warp; g_wt[i0][p0] = inv;
        int p1 = atomicAdd(&g_cnt[i1], 1);
        g_tok[i1][p1] = warp; g_wt[i1][p1] = ex * inv;
    }
}

// ---------------- fused gate+up GEMM: warp-specialized, 3-stage ring -------
// Block 128(M) x 64(N), BK=32, K=1024. Warps 0-7 consumers (4M x 2N,
// warp tile 32x32 per matrix), warps 8-11 producers (LDG+cvt+STS).
template <bool GATHER>
__global__ __launch_bounds__(384, 1)
void gemm_gateup(const float* __restrict__ X,
                 const float* __restrict__ Wg_all,
                 const float* __restrict__ Wu_all) {
    const int e  = GATHER ? blockIdx.z : 0;
    const int M  = GATHER ? g_cnt[e] : TT;
    const int m0 = blockIdx.y * 128;
    if (m0 >= M) return;
    const int n0 = blockIdx.x * 64;

    extern __shared__ char smem[];
    const uint32_t sbase = smem_u32(smem);
    const int tid = threadIdx.x;
    const int wid = tid >> 5, lane = tid & 31;

    const uint32_t mb_full  = sbase + GU_MBAR;
    const uint32_t mb_empty = sbase + GU_MBAR + 24;
    if (tid == 0) {
#pragma unroll
        for (int s = 0; s < 3; s++) {
            mbar_init(mb_full  + 8 * s, 4);   // 4 producer warps
            mbar_init(mb_empty + 8 * s, 8);   // 8 consumer warps
        }
    }
    __syncthreads();

    if (wid < 8) {
        // ================= consumer =================
        const int wm = wid >> 1, wn = wid & 1;
        const int grp = lane >> 2, qid = lane & 3;
        uint32_t aoff[2];
#pragma unroll
        for (int mt = 0; mt < 2; mt++)
            aoff[mt] = ((wm * 32 + mt * 16 + (lane & 15)) * LDR + ((lane & 16) ? 4 : 0)) * 4;

        float cg[2][4][4], cu[2][4][4];
#pragma unroll
        for (int mt = 0; mt < 2; mt++)
#pragma unroll
            for (int nt = 0; nt < 4; nt++)
#pragma unroll
                for (int i = 0; i < 4; i++) { cg[mt][nt][i] = 0.0f; cu[mt][nt][i] = 0.0f; }

        int s = 0, ph = 0;
        for (int c = 0; c < 32; c++) {
            mbar_wait(mb_full + 8 * s, ph);
            const uint32_t Ab = sbase + s * GU_STAGE;
            const char* Gb = smem + s * GU_STAGE + GU_BG;
            const char* Ub = smem + s * GU_STAGE + GU_BU;
#pragma unroll
            for (int ks = 0; ks < 32; ks += 8) {
                uint32_t a[2][4], bg_[8], bu_[8];
                ldsm4(a[0], Ab + aoff[0] + ks * 4);
                ldsm4(a[1], Ab + aoff[1] + ks * 4);
#pragma unroll
                for (int nt = 0; nt < 4; nt++) {
                    int cb = wn * 32 + nt * 8 + grp;
                    uint32_t r0 = (uint32_t)(ks + qid) * 288 + cb * 4;
                    bg_[nt*2]   = *(const uint32_t*)(Gb + r0);
                    bg_[nt*2+1] = *(const uint32_t*)(Gb + r0 + 4 * 288);
                    bu_[nt*2]   = *(const uint32_t*)(Ub + r0);
                    bu_[nt*2+1] = *(const uint32_t*)(Ub + r0 + 4 * 288);
                }
#pragma unroll
                for (int mt = 0; mt < 2; mt++)
#pragma unroll
                    for (int nt = 0; nt < 4; nt++) {
                        mma8(cg[mt][nt], a[mt], &bg_[nt * 2]);
                        mma8(cu[mt][nt], a[mt], &bu_[nt * 2]);
                    }
            }
            __syncwarp();
            if (lane == 0) mbar_arrive(mb_empty + 8 * s);
            if (++s == 3) { s = 0; ph ^= 1; }
        }

        // epilogue: silu(g)*u
#pragma unroll
        for (int mt = 0; mt < 2; mt++) {
#pragma unroll
            for (int half = 0; half < 2; half++) {
                int m = m0 + wm * 32 + mt * 16 + grp + half * 8;
                if (m >= M) continue;
                float* orow = GATHER ? &g_act[e][m][0] : &g_sact[m][0];
#pragma unroll
                for (int nt = 0; nt < 4; nt++) {
                    int c0 = n0 + wn * 32 + nt * 8 + 2 * qid;
                    float g0 = cg[mt][nt][half * 2 + 0], u0 = cu[mt][nt][half * 2 + 0];
                    float g1 = cg[mt][nt][half * 2 + 1], u1 = cu[mt][nt][half * 2 + 1];
                    float2 o;
                    o.x = (g0 / (1.0f + expf(-g0))) * u0;
                    o.y = (g1 / (1.0f + expf(-g1))) * u1;
                    *(float2*)&orow[c0] = o;
                }
            }
        }
    } else {
        // ================= producer =================
        const int ptid = tid - 256;          // 0..127
        const int base = ptid >> 2;          // 0..31 (A row group / B k-row)
        const int q    = ptid & 3;
        const int akof = q * 8;              // A col offset (floats)

        const float* ap[4];
#pragma unroll
        for (int i = 0; i < 4; i++) {
            int r = m0 + base + 32 * i;
            if (r < M) {
                int tok = GATHER ? g_tok[e][r] : r;
                ap[i] = X + (size_t)tok * HH + akof;
            } else ap[i] = nullptr;
        }
        const float* gptr = Wg_all + (GATHER ? (size_t)e * HH * FF : 0)
                            + (size_t)base * FF + n0 + q * 4;
        const float* uptr = Wu_all + (GATHER ? (size_t)e * HH * FF : 0)
                            + (size_t)base * FF + n0 + q * 4;

        int s = 0, ph = 1;   // first empty-wait passes immediately
        for (int c = 0; c < 32; c++) {
            const int kk = c * 32;
            float4 av[4][2], gv[4], uv[4];
#pragma unroll
            for (int i = 0; i < 4; i++) {
                av[i][0] = ap[i] ? *(const float4*)(ap[i] + kk)     : make_float4(0,0,0,0);
                av[i][1] = ap[i] ? *(const float4*)(ap[i] + kk + 4) : make_float4(0,0,0,0);
            }
#pragma unroll
            for (int i = 0; i < 4; i++) {
                gv[i] = *(const float4*)(gptr + (size_t)kk * FF + i * 16);
                uv[i] = *(const float4*)(uptr + (size_t)kk * FF + i * 16);
            }
            mbar_wait(mb_empty + 8 * s, ph);
            char* Ast = smem + s * GU_STAGE;
#pragma unroll
            for (int i = 0; i < 4; i++) {
                int row = base + 32 * i;
                *(uint4*)(Ast + (row * LDR + akof) * 4)     = cvt4(av[i][0]);
                *(uint4*)(Ast + (row * LDR + akof + 4) * 4) = cvt4(av[i][1]);
            }
            char* Gst = Ast + GU_BG;
            char* Ust = Ast + GU_BU;
#pragma unroll
            for (int i = 0; i < 4; i++) {
                uint32_t off = (uint32_t)base * 288 + (q * 4 + i * 16) * 4;
                *(uint4*)(Gst + off) = cvt4(gv[i]);
                *(uint4*)(Ust + off) = cvt4(uv[i]);
            }
            __syncwarp();
            if (lane == 0) mbar_arrive(mb_full + 8 * s);
            if (++s == 3) { s = 0; ph ^= 1; }
        }
    }
}

// ---------------- down-proj GEMM: warp-specialized, 3-stage ring -----------
// Block 128(M) x 128(N). Consumers 4M x 2N, warp tile 32x64.
template <bool EXPERT>
__global__ __launch_bounds__(384, 1)
void gemm_down(const float* __restrict__ Wd_all,
               float* __restrict__ out) {
    const int e  = EXPERT ? blockIdx.z : 0;
    const int M  = EXPERT ? g_cnt[e] : TT;
    const int m0 = blockIdx.y * 128;
    if (m0 >= M) return;
    const int n0 = blockIdx.x * 128;

    extern __shared__ char smem[];
    const uint32_t sbase = smem_u32(smem);
    const int tid = threadIdx.x;
    const int wid = tid >> 5, lane = tid & 31;

    const uint32_t mb_full  = sbase + DN_MBAR;
    const uint32_t mb_empty = sbase + DN_MBAR + 24;
    if (tid == 0) {
#pragma unroll
        for (int s = 0; s < 3; s++) {
            mbar_init(mb_full  + 8 * s, 4);
            mbar_init(mb_empty + 8 * s, 8);
        }
    }
    __syncthreads();

    const float* Asrc = EXPERT ? &g_act[e][0][0] : &g_sact[0][0];

    if (wid < 8) {
        // ================= consumer =================
        const int wm = wid >> 1, wn = wid & 1;
        const int grp = lane >> 2, qid = lane & 3;
        uint32_t aoff[2];
#pragma unroll
        for (int mt = 0; mt < 2; mt++)
            aoff[mt] = ((wm * 32 + mt * 16 + (lane & 15)) * LDR + ((lane & 16) ? 4 : 0)) * 4;

        float cc[2][8][4];
#pragma unroll
        for (int mt = 0; mt < 2; mt++)
#pragma unroll
            for (int nt = 0; nt < 8; nt++)
#pragma unroll
                for (int i = 0; i < 4; i++) cc[mt][nt][i] = 0.0f;

        int s = 0, ph = 0;
        for (int c = 0; c < 32; c++) {
            mbar_wait(mb_full + 8 * s, ph);
            const uint32_t Ab = sbase + s * DN_STAGE;
            const char* Bb = smem + s * DN_STAGE + DN_B;
#pragma unroll
            for (int ks = 0; ks < 32; ks += 8) {
                uint32_t a[2][4], b_[16];
                ldsm4(a[0], Ab + aoff[0] + ks * 4);
                ldsm4(a[1], Ab + aoff[1] + ks * 4);
#pragma unroll
                for (int nt = 0; nt < 8; nt++) {
                    int cb = wn * 64 + nt * 8 + grp;
                    uint32_t r0 = (uint32_t)(ks + qid) * 544 + cb * 4;
                    b_[nt*2]   = *(const uint32_t*)(Bb + r0);
                    b_[nt*2+1] = *(const uint32_t*)(Bb + r0 + 4 * 544);
                }
#pragma unroll
                for (int mt = 0; mt < 2; mt++)
#pragma unroll
                    for (int nt = 0; nt < 8; nt++)
                        mma8(cc[mt][nt], a[mt], &b_[nt * 2]);
            }
            __syncwarp();
            if (lane == 0) mbar_arrive(mb_empty + 8 * s);
            if (++s == 3) { s = 0; ph ^= 1; }
        }

#pragma unroll
        for (int mt = 0; mt < 2; mt++) {
#pragma unroll
            for (int half = 0; half < 2; half++) {
                int m = m0 + wm * 32 + mt * 16 + grp + half * 8;
                if (m >= M) continue;
                if (EXPERT) {
                    int tok = g_tok[e][m];
                    float w = g_wt[e][m];
                    float* orow = out + (size_t)tok * HH;
#pragma unroll
                    for (int nt = 0; nt < 8; nt++) {
                        int c0 = n0 + wn * 64 + nt * 8 + 2 * qid;
                        atomicAdd(&orow[c0],     w * cc[mt][nt][half * 2 + 0]);
                        atomicAdd(&orow[c0 + 1], w * cc[mt][nt][half * 2 + 1]);
                    }
                } else {
                    float* orow = out + (size_t)m * HH;
#pragma unroll
                    for (int nt = 0; nt < 8; nt++) {
                        int c0 = n0 + wn * 64 + nt * 8 + 2 * qid;
                        float2 o = make_float2(cc[mt][nt][half * 2 + 0],
                                               cc[mt][nt][half * 2 + 1]);
                        *(float2*)&orow[c0] = o;
                    }
                }
            }
        }
    } else {
        // ================= producer =================
        const int ptid = tid - 256;
        const int base = ptid >> 2;
        const int q    = ptid & 3;
        const int akof = q * 8;

        const float* ap[4];
#pragma unroll
        for (int i = 0; i < 4; i++) {
            int r = m0 + base + 32 * i;
            ap[i] = (r < M) ? (Asrc + (size_t)r * FF + akof) : nullptr;
        }
        const float* wptr = Wd_all + (EXPERT ? (size_t)e * FF * HH : 0)
                            + (size_t)base * HH + n0 + q * 4;

        int s = 0, ph = 1;
        for (int c = 0; c < 32; c++) {
            const int kk = c * 32;
            float4 av[4][2], bv[8];
#pragma unroll
            for (int i = 0; i < 4; i++) {
                av[i][0] = ap[i] ? *(const float4*)(ap[i] + kk)     : make_float4(0,0,0,0);
                av[i][1] = ap[i] ? *(const float4*)(ap[i] + kk + 4) : make_float4(0,0,0,0);
            }
#pragma unroll
            for (int i = 0; i < 8; i++)
                bv[i] = *(const float4*)(wptr + (size_t)kk * HH + i * 16);

            mbar_wait(mb_empty + 8 * s, ph);
            char* Ast = smem + s * DN_STAGE;
#pragma unroll
            for (int i = 0; i < 4; i++) {
                int row = base + 32 * i;
                *(uint4*)(Ast + (row * LDR + akof) * 4)     = cvt4(av[i][0]);
                *(uint4*)(Ast + (row * LDR + akof + 4) * 4) = cvt4(av[i][1]);
            }
            char* Bst = Ast + DN_B;
#pragma unroll
            for (int i = 0; i < 8; i++) {
                uint32_t off = (uint32_t)base * 544 + (q * 4 + i * 16) * 4;
                *(uint4*)(Bst + off) = cvt4(bv[i]);
            }
            __syncwarp();
            if (lane == 0) mbar_arrive(mb_full + 8 * s);
            if (++s == 3) { s = 0; ph ^= 1; }
        }
    }
}

// ---------------- launch ---------------------------------------------------
extern "C" void kernel_launch(void* const* d_in, const int* in_sizes, int n_in,
                              void* d_out, int out_size) {
    const float* x   = (const float*)d_in[0];
    const float* wg  = (const float*)d_in[1];
    const float* wgp = (const float*)d_in[2];
    const float* wup = (const float*)d_in[3];
    const float* wdp = (const float*)d_in[4];
    const float* wsg = (const float*)d_in[5];
    const float* wsu = (const float*)d_in[6];
    const float* wsd = (const float*)d_in[7];
    float* out = (float*)d_out;

    cudaFuncSetAttribute(gemm_gateup<false>, cudaFuncAttributeMaxDynamicSharedMemorySize, GU_BYTES);
    cudaFuncSetAttribute(gemm_gateup<true>,  cudaFuncAttributeMaxDynamicSharedMemorySize, GU_BYTES);
    cudaFuncSetAttribute(gemm_down<false>,   cudaFuncAttributeMaxDynamicSharedMemorySize, DN_BYTES);
    cudaFuncSetAttribute(gemm_down<true>,    cudaFuncAttributeMaxDynamicSharedMemorySize, DN_BYTES);

    int tail = out_size - TT * HH;
    int init_n = (tail > EE ? tail : EE);
    init_kernel<<<(init_n + 255) / 256, 256>>>(out, out_size);

    router_kernel<<<TT / 8, 256>>>(x, wg);

    dim3 gs1(FF / 64, TT / 128, 1);
    gemm_gateup<false><<<gs1, 384, GU_BYTES>>>(x, wsg, wsu);

    dim3 ge1(FF / 64, TT / 128, EE);
    gemm_gateup<true><<<ge1, 384, GU_BYTES>>>(x, wgp, wup);

    dim3 gs2(HH / 128, TT / 128, 1);
    gemm_down<false><<<gs2, 384, DN_BYTES>>>(wsd, out);   // plain store: initializes out

    dim3 ge2(HH / 128, TT / 128, EE);
    gemm_down<true><<<ge2, 384, DN_BYTES>>>(wdp, out);    // weighted atomicAdd combine
}